// round 6
// baseline (speedup 1.0000x reference)
#include <cuda_runtime.h>

// LossGenerator: T=11, H=W=2048. Inputs u=output, f1, each [11,1,2048,2048] f32.
// Output: [phy, bc] f32. Single fused kernel.
// Row-marching phy pass: each thread owns 1 column, marches 8 rows, keeping
// um1[11], u0[11] state so each u row is loaded from memory ONCE (22 LDG/row
// instead of 44). Overlapping warps (32 lanes -> 30 outputs) make the
// horizontal halo pure-shuffle with zero edge gmem loads.

#define HH 2048
#define WI 2048
static const size_t HWs = (size_t)HH * (size_t)WI;

#define RROWS   8
#define WSEGS   9        // ceil(2046 / 240) output column strips of 240
#define HGRPS   256      // ceil(2046 / 8) row groups
#define NB_BC   10
#define NB_PHY  (WSEGS * HGRPS)
#define NB_TOT  (NB_BC + NB_PHY)

__device__ double   g_phy;
__device__ double   g_bc;
__device__ unsigned g_count;

constexpr double PREFD = 3.5682482323055424;  // 0.1^{-0.5}/Gamma(1.5)
constexpr double WQ[10] = {
    1.0,
    0.41421356237309515,
    0.31783724519578215,
    0.26794919243112270,
    0.23606797749978969,
    0.21342176528338802,
    0.19626156828141264,
    0.18267581368159972,
    0.17157287525380971,
    0.16227766016837933
};

__device__ __forceinline__ void block_reduce_add(double v, double* target, int tid) {
    #pragma unroll
    for (int o = 16; o > 0; o >>= 1)
        v += __shfl_down_sync(0xffffffffu, v, o);
    __shared__ double sr[8];
    int lane = tid & 31, wid = tid >> 5;
    if (lane == 0) sr[wid] = v;
    __syncthreads();
    if (wid == 0) {
        v = (lane < 8) ? sr[lane] : 0.0;
        #pragma unroll
        for (int o = 4; o > 0; o >>= 1)
            v += __shfl_down_sync(0xffffffffu, v, o);
        if (lane == 0) atomicAdd(target, v);
    }
}

__global__ __launch_bounds__(256, 4) void fused_kernel(const float* __restrict__ u,
                                                       const float* __restrict__ f1,
                                                       float* __restrict__ out) {
    const int tid = threadIdx.x;
    const int bid = blockIdx.x;

    if (bid < NB_BC) {
        // ---------------- boundary-condition loss ----------------
        const int it = bid;                      // time slice it+1
        const float* ut = u + (size_t)(it + 1) * HWs;
        const float tval = 0.1f + 0.1f * (float)it;
        const float tt = powf(tval, 1.5f);

        double v = 0.0;
        #pragma unroll
        for (int jb = 0; jb < 8; jb++) {
            const int j = jb * 256 + tid;        // 0..2047
            const float xj = (float)j * (1.0f / 2047.0f);
            const float x1b = tt * sinf(6.2831853071795862f * xj);

            const float l  = ut[(size_t)j * WI];
            const float r  = ut[(size_t)j * WI + (WI - 1)];
            const float tp = ut[j];
            const float bt = ut[(size_t)(HH - 1) * WI + j];

            const float dl = l - x1b, dr = r - x1b, du = tp - x1b, db = bt - x1b;
            v += (double)(dl * dl + dr * dr + du * du + db * db);
        }
        block_reduce_add(v, &g_bc, tid);
    } else {
        // ---------------- physics residual loss ----------------
        const int b    = bid - NB_BC;
        const int wseg = b >> 8;                 // 0..8
        const int hgrp = b & 255;                // 0..255
        const int lane = tid & 31;
        const int wrp  = tid >> 5;               // 0..7

        // Overlapping-warp column mapping: warp spans 32 cols, outputs 30.
        const int wout = wseg * 240 + wrp * 30 + lane - 1;   // -1 .. 2190
        int wl = wout < 0 ? 0 : wout;                        // clamped load col
        if (wl > WI - 1) wl = WI - 1;
        const float msk = (lane >= 1 && lane <= 30 &&
                           wout >= 1 && wout <= WI - 2) ? 1.0f : 0.0f;

        const int h0 = 1 + hgrp * RROWS;         // first output row

        const float A = 0.34520446044393f;
        const float B = 0.309591078922457f;
        const float C = -2.619182157203629f;
        const float KLAP = 0.01f * 4194304.0f;   // kappa / DX^2

        const float fPW[10] = {
            (float)(PREFD * WQ[0]), (float)(PREFD * WQ[1]), (float)(PREFD * WQ[2]),
            (float)(PREFD * WQ[3]), (float)(PREFD * WQ[4]), (float)(PREFD * WQ[5]),
            (float)(PREFD * WQ[6]), (float)(PREFD * WQ[7]), (float)(PREFD * WQ[8]),
            (float)(PREFD * WQ[9])
        };
        const float fPD[10] = {
            0.0f,
            (float)(PREFD * (WQ[0] - WQ[1])), (float)(PREFD * (WQ[1] - WQ[2])),
            (float)(PREFD * (WQ[2] - WQ[3])), (float)(PREFD * (WQ[3] - WQ[4])),
            (float)(PREFD * (WQ[4] - WQ[5])), (float)(PREFD * (WQ[5] - WQ[6])),
            (float)(PREFD * (WQ[6] - WQ[7])), (float)(PREFD * (WQ[7] - WQ[8])),
            (float)(PREFD * (WQ[8] - WQ[9]))
        };
        const float PREFF = (float)PREFD;

        float acc = 0.0f;

        // Marching state: rows h-1 and h for all 11 time slices.
        float um1[11], u0[11];
        {
            const size_t rm1 = (size_t)(h0 - 1) * WI + (size_t)wl;
            #pragma unroll
            for (int t = 0; t < 11; t++) {
                um1[t] = u[(size_t)t * HWs + rm1];
                u0[t]  = u[(size_t)t * HWs + rm1 + WI];
            }
        }

        size_t rowp1 = (size_t)(h0 + 1) * WI + (size_t)wl;  // load row h+1
        size_t rowf  = (size_t)h0 * WI + (size_t)wl;        // f at row h

        for (int r = 0; r < RROWS; r++) {
            const int h = h0 + r;
            if (h > HH - 2) break;                // warp-uniform

            float up1[11];
            #pragma unroll
            for (int t = 0; t < 11; t++)
                up1[t] = u[(size_t)t * HWs + rowp1];

            #pragma unroll
            for (int t = 0; t < 11; t++) {
                const float fv = f1[(size_t)t * HWs + rowf];
                const float ca = um1[t] + up1[t];
                const float u0t = u0[t];
                const float q = fmaf(A, ca, B * u0t);
                const float qL = __shfl_up_sync(0xffffffffu, q, 1);
                const float qR = __shfl_down_sync(0xffffffffu, q, 1);
                const float conv = qL + qR + fmaf(B, ca, C * u0t);
                float fu = u0t - fv - KLAP * conv;
                if (t > 0) {
                    float Dv = PREFF * u0t - fPW[t - 1] * u0[0];
                    #pragma unroll
                    for (int k = 1; k < t; k++)
                        Dv -= fPD[t - k] * u0[k];
                    fu += Dv;
                }
                fu *= msk;
                acc = fmaf(fu, fu, acc);
                um1[t] = u0t;                     // rotate (u0 kept for D of later t)
            }
            #pragma unroll
            for (int t = 0; t < 11; t++)
                u0[t] = up1[t];

            rowp1 += WI;
            rowf  += WI;
        }

        block_reduce_add((double)acc, &g_phy, tid);
    }

    // ---------------- last-block finalize + reset ----------------
    if (tid == 0) {
        __threadfence();
        unsigned prev = atomicAdd(&g_count, 1u);
        if (prev == NB_TOT - 1) {
            out[0] = (float)(2.0 * g_phy / 46047276.0);   // 11*2046*2046
            out[1] = (float)(g_bc / 41943040.0);          // 10*2048*2048
            g_phy = 0.0;
            g_bc  = 0.0;
            g_count = 0u;
            __threadfence();
        }
    }
}

extern "C" void kernel_launch(void* const* d_in, const int* in_sizes, int n_in,
                              void* d_out, int out_size) {
    const float* u  = (const float*)d_in[0];
    const float* f1 = (const float*)d_in[1];
    float* out = (float*)d_out;

    fused_kernel<<<NB_TOT, 256>>>(u, f1, out);
}

// round 7
// speedup vs baseline: 1.9848x; 1.9848x over previous
#include <cuda_runtime.h>

// LossGenerator: T=11, H=W=2048. Inputs u=output, f1, each [11,1,2048,2048] f32.
// Output: [phy, bc] f32. Single fused kernel.
// R5 skeleton (float2 lanes, separable stencil q-trick, 2 shuffles/t) plus an
// explicit 1-deep software pipeline: loads for time slice t+1 are issued before
// computing slice t, keeping ~2 load batches in flight per warp.

#define HH 2048
#define WI 2048
static const size_t HWs = (size_t)HH * (size_t)WI;

#define NB_BC   10
#define NB_PHY  8192     // 32 w-segments (64 px) x 256 row-groups (8 rows)
#define NB_TOT  (NB_BC + NB_PHY)

__device__ double   g_phy;
__device__ double   g_bc;
__device__ unsigned g_count;

constexpr double PREFD = 3.5682482323055424;  // 0.1^{-0.5}/Gamma(1.5)
constexpr double WQ[10] = {
    1.0,
    0.41421356237309515,
    0.31783724519578215,
    0.26794919243112270,
    0.23606797749978969,
    0.21342176528338802,
    0.19626156828141264,
    0.18267581368159972,
    0.17157287525380971,
    0.16227766016837933
};

__device__ __forceinline__ void block_reduce_add(double v, double* target, int tid) {
    #pragma unroll
    for (int o = 16; o > 0; o >>= 1)
        v += __shfl_down_sync(0xffffffffu, v, o);
    __shared__ double sr[8];
    int lane = tid & 31, wid = tid >> 5;
    if (lane == 0) sr[wid] = v;
    __syncthreads();
    if (wid == 0) {
        v = (lane < 8) ? sr[lane] : 0.0;
        #pragma unroll
        for (int o = 4; o > 0; o >>= 1)
            v += __shfl_down_sync(0xffffffffu, v, o);
        if (lane == 0) atomicAdd(target, v);
    }
}

__global__ __launch_bounds__(256, 4) void fused_kernel(const float* __restrict__ u,
                                                       const float* __restrict__ f1,
                                                       float* __restrict__ out) {
    const int tid = threadIdx.x;
    const int bid = blockIdx.x;

    if (bid < NB_BC) {
        // ---------------- boundary-condition loss ----------------
        const int it = bid;                      // time slice it+1
        const float* ut = u + (size_t)(it + 1) * HWs;
        const float tval = 0.1f + 0.1f * (float)it;
        const float tt = powf(tval, 1.5f);

        double v = 0.0;
        #pragma unroll
        for (int jb = 0; jb < 8; jb++) {
            const int j = jb * 256 + tid;        // 0..2047
            const float xj = (float)j * (1.0f / 2047.0f);
            const float x1b = tt * sinf(6.2831853071795862f * xj);

            const float l  = ut[(size_t)j * WI];
            const float r  = ut[(size_t)j * WI + (WI - 1)];
            const float tp = ut[j];
            const float bt = ut[(size_t)(HH - 1) * WI + j];

            const float dl = l - x1b, dr = r - x1b, du = tp - x1b, db = bt - x1b;
            v += (double)(dl * dl + dr * dr + du * du + db * db);
        }
        block_reduce_add(v, &g_bc, tid);
    } else {
        // ---------------- physics residual loss ----------------
        const int b    = bid - NB_BC;
        const int lane = tid & 31;
        const int wrp  = tid >> 5;               // 0..7
        const int seg  = b & 31;                 // w segment of 64 px
        const int h    = 1 + (b >> 5) * 8 + wrp; // row, 1..2048 (mask > 2046)
        const int w0   = seg * 64 + lane * 2;    // 0..2046, 8B aligned

        float acc = 0.0f;

        if (h <= HH - 2) {
            const float A = 0.34520446044393f;
            const float B = 0.309591078922457f;
            const float C = -2.619182157203629f;
            const float KLAP = 0.01f * 4194304.0f;     // kappa / DX^2

            const float fPW[10] = {
                (float)(PREFD * WQ[0]), (float)(PREFD * WQ[1]), (float)(PREFD * WQ[2]),
                (float)(PREFD * WQ[3]), (float)(PREFD * WQ[4]), (float)(PREFD * WQ[5]),
                (float)(PREFD * WQ[6]), (float)(PREFD * WQ[7]), (float)(PREFD * WQ[8]),
                (float)(PREFD * WQ[9])
            };
            const float fPD[10] = {
                0.0f,
                (float)(PREFD * (WQ[0] - WQ[1])), (float)(PREFD * (WQ[1] - WQ[2])),
                (float)(PREFD * (WQ[2] - WQ[3])), (float)(PREFD * (WQ[3] - WQ[4])),
                (float)(PREFD * (WQ[4] - WQ[5])), (float)(PREFD * (WQ[5] - WQ[6])),
                (float)(PREFD * (WQ[6] - WQ[7])), (float)(PREFD * (WQ[7] - WQ[8])),
                (float)(PREFD * (WQ[8] - WQ[9]))
            };
            const float PREFF = (float)PREFD;

            const float msk0 = (w0 == 0)      ? 0.0f : 1.0f;
            const float msk1 = (w0 == WI - 2) ? 0.0f : 1.0f;
            // Edge-lane gmem fetch: lane 0 needs q at w0-1, lane 31 at w0+2.
            const bool edge = ((lane == 0) && (w0 > 0)) ||
                              ((lane == 31) && (w0 < WI - 2));
            const int  eo   = (lane == 0) ? -1 : 2;

            float uc[11][2];
            const size_t base = (size_t)(h - 1) * WI + (size_t)w0;

            // ---- pipeline stage registers ----
            float2 cA, cM, cB, cF;          // current slice loads
            float  ceT = 0.f, ceM = 0.f, ceB = 0.f;  // current edge scalars
            {
                const float* pt = u + base;            // t = 0, row h-1
                const float* pm = pt + WI;
                const float* pb = pm + WI;
                cA = *(const float2*)pt;
                cM = *(const float2*)pm;
                cB = *(const float2*)pb;
                cF = *(const float2*)(f1 + base + WI);
                if (edge) { ceT = pt[eo]; ceM = pm[eo]; ceB = pb[eo]; }
            }

            #pragma unroll
            for (int t = 0; t < 11; t++) {
                // ---- prefetch slice t+1 ----
                float2 nA, nM, nB, nF;
                float  neT = 0.f, neM = 0.f, neB = 0.f;
                if (t < 10) {
                    const float* pt = u + (size_t)(t + 1) * HWs + base;
                    const float* pm = pt + WI;
                    const float* pb = pm + WI;
                    nA = *(const float2*)pt;
                    nM = *(const float2*)pm;
                    nB = *(const float2*)pb;
                    nF = *(const float2*)(f1 + (size_t)(t + 1) * HWs + base + WI);
                    if (edge) { neT = pt[eo]; neM = pm[eo]; neB = pb[eo]; }
                }

                // ---- compute slice t from current registers ----
                float qE = 0.0f;
                if (edge)
                    qE = fmaf(A, ceT + ceB, B * ceM);

                const float ca0 = cA.x + cB.x, ca1 = cA.y + cB.y;
                const float q0 = fmaf(A, ca0, B * cM.x);
                const float q1 = fmaf(A, ca1, B * cM.y);

                float qL = __shfl_up_sync(0xffffffffu, q1, 1);
                float qR = __shfl_down_sync(0xffffffffu, q0, 1);
                if (lane == 0)  qL = qE;
                if (lane == 31) qR = qE;

                const float qa[4] = { qL, q0, q1, qR };
                const float ca[2] = { ca0, ca1 };
                const float mc[2] = { cM.x, cM.y };
                const float ff[2] = { cF.x, cF.y };
                const float msk[2] = { msk0, msk1 };

                #pragma unroll
                for (int j = 0; j < 2; j++) {
                    const float center = mc[j];
                    const float conv = qa[j] + qa[j + 2]
                                     + fmaf(B, ca[j], C * center);
                    float fu = center - ff[j] - KLAP * conv;
                    if (t > 0) {
                        float Dv = PREFF * center - fPW[t - 1] * uc[0][j];
                        #pragma unroll
                        for (int k = 1; k < t; k++)
                            Dv -= fPD[t - k] * uc[k][j];
                        fu += Dv;
                    }
                    fu *= msk[j];
                    acc = fmaf(fu, fu, acc);
                    uc[t][j] = center;
                }

                // ---- rotate pipeline ----
                cA = nA; cM = nM; cB = nB; cF = nF;
                ceT = neT; ceM = neM; ceB = neB;
            }
        }

        block_reduce_add((double)acc, &g_phy, tid);
    }

    // ---------------- last-block finalize + reset ----------------
    if (tid == 0) {
        __threadfence();
        unsigned prev = atomicAdd(&g_count, 1u);
        if (prev == NB_TOT - 1) {
            out[0] = (float)(2.0 * g_phy / 46047276.0);   // 11*2046*2046
            out[1] = (float)(g_bc / 41943040.0);          // 10*2048*2048
            g_phy = 0.0;
            g_bc  = 0.0;
            g_count = 0u;
            __threadfence();
        }
    }
}

extern "C" void kernel_launch(void* const* d_in, const int* in_sizes, int n_in,
                              void* d_out, int out_size) {
    const float* u  = (const float*)d_in[0];
    const float* f1 = (const float*)d_in[1];
    float* out = (float*)d_out;

    fused_kernel<<<NB_TOT, 256>>>(u, f1, out);
}